// round 1
// baseline (speedup 1.0000x reference)
#include <cuda_runtime.h>

#define NTOK 4096
#define DIM  1024
#define HDIM 4096
#define NE   8

#define TM 64
#define TN 64
#define TK 16
#define SSTRIDE 68   // smem row stride (floats): keeps 16B alignment, reduces conflicts

__device__ int   g_counts[NE];
__device__ int   g_tlist[NE * NTOK];
__device__ float g_h[(size_t)NTOK * HDIM];   // relu(x@fc)^2 scratch, 64 MB

// ---------------------------------------------------------------------------
__global__ void init_counts_kernel() {
    if (threadIdx.x < NE) g_counts[threadIdx.x] = 0;
}

// One warp per token: fp32 logits, first-max argmax (matches jnp.argmax),
// atomic compaction into per-expert token lists.
__global__ void router_kernel(const float* __restrict__ x,
                              const float* __restrict__ rw) {
    int warp = (blockIdx.x * blockDim.x + threadIdx.x) >> 5;
    int lane = threadIdx.x & 31;
    if (warp >= NTOK) return;
    const float* xr = x + (size_t)warp * DIM;
    float best = -1e30f;
    int bestE = 0;
#pragma unroll
    for (int e = 0; e < NE; e++) {
        const float* wr = rw + e * DIM;
        float p = 0.f;
        for (int k = lane; k < DIM; k += 32) p += xr[k] * wr[k];
#pragma unroll
        for (int o = 16; o; o >>= 1) p += __shfl_xor_sync(0xffffffffu, p, o);
        if (p > best) { best = p; bestE = e; }   // strict > keeps earliest index
    }
    if (lane == 0) {
        int slot = atomicAdd(&g_counts[bestE], 1);
        g_tlist[bestE * NTOK + slot] = warp;
    }
}

// ---------------------------------------------------------------------------
// GEMM1: for expert e, h[token, n] = relu( x[token,:] @ fc_e[:, n] )^2
// fc layout [E, D, HD] (n contiguous). A rows gathered via token list.
__global__ __launch_bounds__(256) void gemm1_kernel(const float* __restrict__ x,
                                                    const float* __restrict__ fc) {
    const int e = blockIdx.z;
    const int count = g_counts[e];
    const int m0 = blockIdx.y * TM;
    if (m0 >= count) return;
    const int n0 = blockIdx.x * TN;

    __shared__ float As[TK][SSTRIDE];   // transposed: As[k][row]
    __shared__ float Bs[TK][SSTRIDE];   // Bs[k][col]
    __shared__ int   toks[TM];

    const int tid = threadIdx.x;
    const int tx = tid & 15;            // 16 col groups
    const int ty = tid >> 4;            // 16 row groups

    if (tid < TM) {
        int mg = m0 + tid;
        toks[tid] = (mg < count) ? g_tlist[e * NTOK + mg] : -1;
    }
    __syncthreads();

    // A-load mapping: row = tid/4, kg = tid%4 -> k = kg*4 (float4)
    const int a_row = tid >> 2;
    const int a_k   = (tid & 3) * 4;
    // B-load mapping: k = tid/16, ng = tid%16 -> n = ng*4 (float4)
    const int b_k = tid >> 4;
    const int b_n = (tid & 15) * 4;

    const float* fce = fc + (size_t)e * DIM * HDIM;

    float acc[4][4];
#pragma unroll
    for (int i = 0; i < 4; i++)
#pragma unroll
        for (int j = 0; j < 4; j++) acc[i][j] = 0.f;

    const int tokA = toks[a_row];

    for (int k0 = 0; k0 < DIM; k0 += TK) {
        // load A tile (gathered, transposed into smem)
        float4 av = make_float4(0.f, 0.f, 0.f, 0.f);
        if (tokA >= 0)
            av = *(const float4*)(x + (size_t)tokA * DIM + k0 + a_k);
        As[a_k + 0][a_row] = av.x;
        As[a_k + 1][a_row] = av.y;
        As[a_k + 2][a_row] = av.z;
        As[a_k + 3][a_row] = av.w;
        // load B tile
        float4 bv = *(const float4*)(fce + (size_t)(k0 + b_k) * HDIM + n0 + b_n);
        *(float4*)&Bs[b_k][b_n] = bv;
        __syncthreads();

#pragma unroll
        for (int kk = 0; kk < TK; kk++) {
            float4 a = *(const float4*)&As[kk][ty * 4];
            float4 b = *(const float4*)&Bs[kk][tx * 4];
            acc[0][0] += a.x * b.x; acc[0][1] += a.x * b.y; acc[0][2] += a.x * b.z; acc[0][3] += a.x * b.w;
            acc[1][0] += a.y * b.x; acc[1][1] += a.y * b.y; acc[1][2] += a.y * b.z; acc[1][3] += a.y * b.w;
            acc[2][0] += a.z * b.x; acc[2][1] += a.z * b.y; acc[2][2] += a.z * b.z; acc[2][3] += a.z * b.w;
            acc[3][0] += a.w * b.x; acc[3][1] += a.w * b.y; acc[3][2] += a.w * b.z; acc[3][3] += a.w * b.w;
        }
        __syncthreads();
    }

#pragma unroll
    for (int i = 0; i < 4; i++) {
        int r = ty * 4 + i;
        int tok = toks[r];
        if (tok < 0) continue;
        float4 v;
        float t0 = fmaxf(acc[i][0], 0.f);
        float t1 = fmaxf(acc[i][1], 0.f);
        float t2 = fmaxf(acc[i][2], 0.f);
        float t3 = fmaxf(acc[i][3], 0.f);
        v.x = t0 * t0; v.y = t1 * t1; v.z = t2 * t2; v.w = t3 * t3;
        *(float4*)(g_h + (size_t)tok * HDIM + n0 + tx * 4) = v;
    }
}

// ---------------------------------------------------------------------------
// GEMM2: out[token, d] = h[token,:] @ proj_e[d, :]   (proj layout [E, D, HD], k=h contiguous)
__global__ __launch_bounds__(256) void gemm2_kernel(const float* __restrict__ proj,
                                                    float* __restrict__ out) {
    const int e = blockIdx.z;
    const int count = g_counts[e];
    const int m0 = blockIdx.y * TM;
    if (m0 >= count) return;
    const int n0 = blockIdx.x * TN;

    __shared__ float As[TK][SSTRIDE];
    __shared__ float Bs[TK][SSTRIDE];
    __shared__ int   toks[TM];

    const int tid = threadIdx.x;
    const int tx = tid & 15;
    const int ty = tid >> 4;

    if (tid < TM) {
        int mg = m0 + tid;
        toks[tid] = (mg < count) ? g_tlist[e * NTOK + mg] : -1;
    }
    __syncthreads();

    const int a_row = tid >> 2;
    const int a_k   = (tid & 3) * 4;
    // B: n-major rows, k contiguous -> load [n, k..k+3] and transpose into smem
    const int b_n  = tid >> 2;          // 64 n values
    const int b_k  = (tid & 3) * 4;     // 4 k groups

    const float* pe = proj + (size_t)e * DIM * HDIM;

    float acc[4][4];
#pragma unroll
    for (int i = 0; i < 4; i++)
#pragma unroll
        for (int j = 0; j < 4; j++) acc[i][j] = 0.f;

    const int tokA = toks[a_row];

    for (int k0 = 0; k0 < HDIM; k0 += TK) {
        float4 av = make_float4(0.f, 0.f, 0.f, 0.f);
        if (tokA >= 0)
            av = *(const float4*)(g_h + (size_t)tokA * HDIM + k0 + a_k);
        As[a_k + 0][a_row] = av.x;
        As[a_k + 1][a_row] = av.y;
        As[a_k + 2][a_row] = av.z;
        As[a_k + 3][a_row] = av.w;

        float4 bv = *(const float4*)(pe + (size_t)(n0 + b_n) * HDIM + k0 + b_k);
        Bs[b_k + 0][b_n] = bv.x;
        Bs[b_k + 1][b_n] = bv.y;
        Bs[b_k + 2][b_n] = bv.z;
        Bs[b_k + 3][b_n] = bv.w;
        __syncthreads();

#pragma unroll
        for (int kk = 0; kk < TK; kk++) {
            float4 a = *(const float4*)&As[kk][ty * 4];
            float4 b = *(const float4*)&Bs[kk][tx * 4];
            acc[0][0] += a.x * b.x; acc[0][1] += a.x * b.y; acc[0][2] += a.x * b.z; acc[0][3] += a.x * b.w;
            acc[1][0] += a.y * b.x; acc[1][1] += a.y * b.y; acc[1][2] += a.y * b.z; acc[1][3] += a.y * b.w;
            acc[2][0] += a.z * b.x; acc[2][1] += a.z * b.y; acc[2][2] += a.z * b.z; acc[2][3] += a.z * b.w;
            acc[3][0] += a.w * b.x; acc[3][1] += a.w * b.y; acc[3][2] += a.w * b.z; acc[3][3] += a.w * b.w;
        }
        __syncthreads();
    }

#pragma unroll
    for (int i = 0; i < 4; i++) {
        int r = ty * 4 + i;
        int tok = toks[r];
        if (tok < 0) continue;
        float4 v = make_float4(acc[i][0], acc[i][1], acc[i][2], acc[i][3]);
        *(float4*)(out + (size_t)tok * DIM + n0 + tx * 4) = v;
    }
}

// ---------------------------------------------------------------------------
extern "C" void kernel_launch(void* const* d_in, const int* in_sizes, int n_in,
                              void* d_out, int out_size) {
    const float* x    = (const float*)d_in[0];
    const float* rw   = (const float*)d_in[1];
    const float* fc   = (const float*)d_in[2];
    const float* proj = (const float*)d_in[3];
    float* out = (float*)d_out;

    init_counts_kernel<<<1, 32>>>();
    router_kernel<<<(NTOK * 32) / 256, 256>>>(x, rw);

    dim3 g1(HDIM / TN, NTOK / TM, NE);   // 64 x 64 x 8, most blocks early-exit
    gemm1_kernel<<<g1, 256>>>(x, fc);

    dim3 g2(DIM / TN, NTOK / TM, NE);    // 16 x 64 x 8
    gemm2_kernel<<<g2, 256>>>(proj, out);
}